// round 1
// baseline (speedup 1.0000x reference)
#include <cuda_runtime.h>
#include <math_constants.h>

// Per-cluster precomputed parameters:
//   g_params[j] = { g00, 2*g01, g11, log_softmax(w)_j + 0.5*log(det_j) }
//   g_mu[j]     = { mu_j0, mu_j1 }
#define MAX_M 1024
__device__ float4 g_params[MAX_M];
__device__ float2 g_mu[MAX_M];

// ---------------------------------------------------------------------------
// Prep kernel: one block of 1024 threads. Computes gamma = A A^T / 2,
// determinant, log_softmax(w), and packs params.
// ---------------------------------------------------------------------------
__global__ void gmm_prep_kernel(const float* __restrict__ mu,
                                const float* __restrict__ A,
                                const float* __restrict__ w,
                                int M) {
    __shared__ float red[1024];
    int j = threadIdx.x;

    float wj = (j < M) ? w[j] : -CUDART_INF_F;

    // max-reduce w
    red[j] = wj;
    __syncthreads();
    for (int s = 512; s > 0; s >>= 1) {
        if (j < s) red[j] = fmaxf(red[j], red[j + s]);
        __syncthreads();
    }
    float wmax = red[0];
    __syncthreads();

    // sum exp(w - wmax)
    red[j] = (j < M) ? __expf(wj - wmax) : 0.0f;
    __syncthreads();
    for (int s = 512; s > 0; s >>= 1) {
        if (j < s) red[j] += red[j + s];
        __syncthreads();
    }
    float lse_w = wmax + __logf(red[0]);

    if (j < M) {
        float a00 = A[j * 4 + 0];
        float a01 = A[j * 4 + 1];
        float a10 = A[j * 4 + 2];
        float a11 = A[j * 4 + 3];
        // gamma = A A^T / 2 (2x2 symmetric)
        float g00 = 0.5f * (a00 * a00 + a01 * a01);
        float g01 = 0.5f * (a00 * a10 + a01 * a11);
        float g11 = 0.5f * (a10 * a10 + a11 * a11);
        float det = g00 * g11 - g01 * g01;
        float logw = (wj - lse_w) + 0.5f * __logf(det);
        g_params[j] = make_float4(g00, 2.0f * g01, g11, logw);
        g_mu[j]     = make_float2(mu[j * 2 + 0], mu[j * 2 + 1]);
    }
}

// ---------------------------------------------------------------------------
// t_ij = logw_j - (x - mu_j)^T gamma_j (x - mu_j)
// q = g00*d0^2 + 2*g01*d0*d1 + g11*d1^2
//   = d0*(g00*d0 + (2*g01)*d1) + g11*d1*d1
// ---------------------------------------------------------------------------
__device__ __forceinline__ float tval(float4 p, float2 m, float x0, float x1) {
    float d0 = x0 - m.x;
    float d1 = x1 - m.y;
    float u  = fmaf(p.x, d0, p.y * d1);
    float q  = fmaf(d0, u, p.z * d1 * d1);
    return p.w - q;
}

// ---------------------------------------------------------------------------
// Main kernel: one sample per thread, all M cluster params staged in shared
// memory (warp-uniform broadcast reads). Two-pass logsumexp:
//   pass 1: mx = max_j t_ij  (4 independent partial maxes for ILP)
//   pass 2: s  = sum_j exp(t_ij - mx)  (4 partial sums)
//   out_i = mx + log(s)
// ---------------------------------------------------------------------------
__global__ __launch_bounds__(128) void gmm_ll_kernel(
    const float* __restrict__ sample,
    float* __restrict__ out,
    int N, int M) {
    __shared__ float4 sp[MAX_M];
    __shared__ float2 smu[MAX_M];

    for (int j = threadIdx.x; j < M; j += blockDim.x) {
        sp[j]  = g_params[j];
        smu[j] = g_mu[j];
    }
    __syncthreads();

    int i = blockIdx.x * blockDim.x + threadIdx.x;
    if (i >= N) return;

    float x0 = sample[2 * i + 0];
    float x1 = sample[2 * i + 1];

    // ---- pass 1: max ----
    float mx0 = -CUDART_INF_F, mx1 = -CUDART_INF_F;
    float mx2 = -CUDART_INF_F, mx3 = -CUDART_INF_F;
    #pragma unroll 4
    for (int j = 0; j < M; j += 4) {
        mx0 = fmaxf(mx0, tval(sp[j + 0], smu[j + 0], x0, x1));
        mx1 = fmaxf(mx1, tval(sp[j + 1], smu[j + 1], x0, x1));
        mx2 = fmaxf(mx2, tval(sp[j + 2], smu[j + 2], x0, x1));
        mx3 = fmaxf(mx3, tval(sp[j + 3], smu[j + 3], x0, x1));
    }
    float mx = fmaxf(fmaxf(mx0, mx1), fmaxf(mx2, mx3));

    // ---- pass 2: sum exp ----
    float s0 = 0.0f, s1 = 0.0f, s2 = 0.0f, s3 = 0.0f;
    #pragma unroll 4
    for (int j = 0; j < M; j += 4) {
        s0 += __expf(tval(sp[j + 0], smu[j + 0], x0, x1) - mx);
        s1 += __expf(tval(sp[j + 1], smu[j + 1], x0, x1) - mx);
        s2 += __expf(tval(sp[j + 2], smu[j + 2], x0, x1) - mx);
        s3 += __expf(tval(sp[j + 3], smu[j + 3], x0, x1) - mx);
    }

    out[i] = mx + __logf((s0 + s1) + (s2 + s3));
}

// ---------------------------------------------------------------------------
// Inputs (metadata order): sample [N,2] f32, mu [M,2] f32, A [M,2,2] f32,
// w [M,1] f32. Output: [N,1] f32.
// ---------------------------------------------------------------------------
extern "C" void kernel_launch(void* const* d_in, const int* in_sizes, int n_in,
                              void* d_out, int out_size) {
    const float* sample = (const float*)d_in[0];
    const float* mu     = (const float*)d_in[1];
    const float* A      = (const float*)d_in[2];
    const float* w      = (const float*)d_in[3];
    float* out = (float*)d_out;

    int N = in_sizes[0] / 2;   // sample: N*D, D=2
    int M = in_sizes[3];       // w: M*1

    gmm_prep_kernel<<<1, 1024>>>(mu, A, w, M);

    int threads = 128;
    int blocks = (N + threads - 1) / threads;
    gmm_ll_kernel<<<blocks, threads>>>(sample, out, N, M);
}

// round 4
// speedup vs baseline: 1.9911x; 1.9911x over previous
#include <cuda_runtime.h>
#include <math_constants.h>

// Per-cluster expanded quadratic in log2 domain, shifted by the global max:
//   t2_j(x) = F_j + A_j*x0^2 + B_j*x1^2 + C_j*x0*x1 + D_j*x0 + E_j*x1
// where all coeffs absorb log2(e) and F absorbs -mx2 (mx2 = max_j log2w_j).
// Packed 2 clusters per 3 float4:
//   [A0,B0,C0,D0] [E0,F0,A1,B1] [C1,D1,E1,F1]
#define MAX_M 1024
#define NPAIR (MAX_M / 2)
__device__ __align__(16) float4 g_coef[NPAIR * 3];  // 24 KB
__device__ float g_mx2;                              // max_j L*logw_j

// ---------------------------------------------------------------------------
// Prep kernel: one block of 1024 threads.
// ---------------------------------------------------------------------------
__global__ void gmm_prep_kernel(const float* __restrict__ mu,
                                const float* __restrict__ A,
                                const float* __restrict__ w,
                                int M) {
    __shared__ float red[1024];
    int j = threadIdx.x;

    float wj = (j < M) ? w[j] : -CUDART_INF_F;

    // --- softmax denominator: max(w) then sum exp ---
    red[j] = wj;
    __syncthreads();
    for (int s = 512; s > 0; s >>= 1) {
        if (j < s) red[j] = fmaxf(red[j], red[j + s]);
        __syncthreads();
    }
    float wmax = red[0];
    __syncthreads();

    red[j] = (j < M) ? __expf(wj - wmax) : 0.0f;
    __syncthreads();
    for (int s = 512; s > 0; s >>= 1) {
        if (j < s) red[j] += red[j + s];
        __syncthreads();
    }
    float lse_w = wmax + __logf(red[0]);
    __syncthreads();

    // --- per-cluster gamma, det, logw ---
    float g00 = 0.f, g01 = 0.f, g11 = 0.f, logw = -CUDART_INF_F;
    float m0 = 0.f, m1 = 0.f;
    if (j < M) {
        float a00 = A[j * 4 + 0];
        float a01 = A[j * 4 + 1];
        float a10 = A[j * 4 + 2];
        float a11 = A[j * 4 + 3];
        g00 = 0.5f * (a00 * a00 + a01 * a01);
        g01 = 0.5f * (a00 * a10 + a01 * a11);
        g11 = 0.5f * (a10 * a10 + a11 * a11);
        float det = g00 * g11 - g01 * g01;
        logw = (wj - lse_w) + 0.5f * __logf(det);  // natural log
        m0 = mu[j * 2 + 0];
        m1 = mu[j * 2 + 1];
    }

    // --- global shift: mx2 = max_j log2-scaled logw ---
    const float L = 1.4426950408889634f;  // log2(e)
    red[j] = L * logw;                    // -inf for padding threads
    __syncthreads();
    for (int s = 512; s > 0; s >>= 1) {
        if (j < s) red[j] = fmaxf(red[j], red[j + s]);
        __syncthreads();
    }
    float mx2 = red[0];
    if (j == 0) g_mx2 = mx2;

    if (j < M) {
        float cA = -L * g00;
        float cB = -L * g11;
        float cC = -L * 2.0f * g01;
        float cD =  L * 2.0f * (g00 * m0 + g01 * m1);
        float cE =  L * 2.0f * (g11 * m1 + g01 * m0);
        float cF =  L * (logw - (g00 * m0 * m0 + 2.0f * g01 * m0 * m1 + g11 * m1 * m1))
                    - mx2;

        float* gp = (float*)g_coef;
        int p = j >> 1;        // pair index
        int h = j & 1;         // half
        int base = p * 12 + h * 6;  // cluster 0 -> floats [0..5], cluster 1 -> [6..11]
        gp[base + 0] = cA;
        gp[base + 1] = cB;
        gp[base + 2] = cC;
        gp[base + 3] = cD;
        gp[base + 4] = cE;
        gp[base + 5] = cF;
    }
}

__device__ __forceinline__ float ex2f(float x) {
    float r;
    asm("ex2.approx.ftz.f32 %0, %1;" : "=f"(r) : "f"(x));
    return r;
}

// ---------------------------------------------------------------------------
// Main kernel: one sample per thread; single pass over all M clusters.
// Per cluster: 5 FFMA -> EX2 -> FADD. Coefficients broadcast from shared.
// ---------------------------------------------------------------------------
__global__ __launch_bounds__(128) void gmm_ll_kernel(
    const float* __restrict__ sample,
    float* __restrict__ out,
    int N, int M) {
    __shared__ __align__(16) float4 sc[NPAIR * 3];

    for (int k = threadIdx.x; k < (M >> 1) * 3; k += blockDim.x)
        sc[k] = g_coef[k];
    __syncthreads();

    int i = blockIdx.x * blockDim.x + threadIdx.x;
    if (i >= N) return;

    float x0 = sample[2 * i + 0];
    float x1 = sample[2 * i + 1];
    float x00 = x0 * x0, x11 = x1 * x1, x01 = x0 * x1;

    const int npair = M >> 1;
    float sa = 0.0f, sb = 0.0f, sc_ = 0.0f, sd = 0.0f;

    // 4 clusters (2 pairs) per iteration; 6 LDS.128, 4 independent chains.
    #pragma unroll 2
    for (int p = 0; p < npair; p += 2) {
        float4 v0 = sc[3 * p + 0];  // A0 B0 C0 D0
        float4 v1 = sc[3 * p + 1];  // E0 F0 A1 B1
        float4 v2 = sc[3 * p + 2];  // C1 D1 E1 F1
        float4 u0 = sc[3 * p + 3];
        float4 u1 = sc[3 * p + 4];
        float4 u2 = sc[3 * p + 5];

        // cluster 2p
        float t0 = fmaf(v1.x, x1, v1.y);     // E*x1 + F
        t0 = fmaf(v0.w, x0,  t0);            // +D*x0
        t0 = fmaf(v0.z, x01, t0);            // +C*x0x1
        t0 = fmaf(v0.y, x11, t0);            // +B*x1^2
        t0 = fmaf(v0.x, x00, t0);            // +A*x0^2

        // cluster 2p+1
        float t1 = fmaf(v2.z, x1, v2.w);
        t1 = fmaf(v2.y, x0,  t1);
        t1 = fmaf(v2.x, x01, t1);
        t1 = fmaf(v1.w, x11, t1);
        t1 = fmaf(v1.z, x00, t1);

        // cluster 2p+2
        float t2 = fmaf(u1.x, x1, u1.y);
        t2 = fmaf(u0.w, x0,  t2);
        t2 = fmaf(u0.z, x01, t2);
        t2 = fmaf(u0.y, x11, t2);
        t2 = fmaf(u0.x, x00, t2);

        // cluster 2p+3
        float t3 = fmaf(u2.z, x1, u2.w);
        t3 = fmaf(u2.y, x0,  t3);
        t3 = fmaf(u2.x, x01, t3);
        t3 = fmaf(u1.w, x11, t3);
        t3 = fmaf(u1.z, x00, t3);

        sa += ex2f(t0);
        sb += ex2f(t1);
        sc_ += ex2f(t2);
        sd += ex2f(t3);
    }

    float s = (sa + sb) + (sc_ + sd);
    out[i] = (g_mx2 + __log2f(s)) * 0.6931471805599453f;
}

// ---------------------------------------------------------------------------
// Inputs (metadata order): sample [N,2] f32, mu [M,2] f32, A [M,2,2] f32,
// w [M,1] f32. Output: [N,1] f32.
// ---------------------------------------------------------------------------
extern "C" void kernel_launch(void* const* d_in, const int* in_sizes, int n_in,
                              void* d_out, int out_size) {
    const float* sample = (const float*)d_in[0];
    const float* mu     = (const float*)d_in[1];
    const float* A      = (const float*)d_in[2];
    const float* w      = (const float*)d_in[3];
    float* out = (float*)d_out;

    int N = in_sizes[0] / 2;
    int M = in_sizes[3];

    gmm_prep_kernel<<<1, 1024>>>(mu, A, w, M);

    int threads = 128;
    int blocks = (N + threads - 1) / threads;
    gmm_ll_kernel<<<blocks, threads>>>(sample, out, N, M);
}